// round 16
// baseline (speedup 1.0000x reference)
#include <cuda_runtime.h>
#include <cuda.h>
#include <cstdint>

__device__ float g_partial[64][64];        // [block][0..31]=s0, [32..63]=s1
__device__ uint32_t g_scr0[2048 * 32];     // U0 * s1, tf32 bits, zero-padded rows
__device__ uint32_t g_scr1[1024 * 32];     // U1 * s0, tf32 bits, zero-padded rows

// ---------------------------------------------------------------------------
// Colsum stage 1: 64 blocks, float4-vectorized, deterministic partials.
// ---------------------------------------------------------------------------
__global__ void colsum_stage1(const float4* __restrict__ U0, int n0_4,
                              const float4* __restrict__ U1, int n1_4) {
    __shared__ float4 red[256];
    const int tid = threadIdx.x;

    float4 acc = make_float4(0.f, 0.f, 0.f, 0.f);
    for (int i = blockIdx.x * 256 + tid; i < n0_4; i += 64 * 256) {
        float4 v = U0[i];
        acc.x += v.x; acc.y += v.y; acc.z += v.z; acc.w += v.w;
    }
    red[tid] = acc;
    __syncthreads();
    if (tid < 8) {
        float4 s = make_float4(0.f, 0.f, 0.f, 0.f);
#pragma unroll
        for (int j = 0; j < 32; j++) {
            float4 v = red[tid + 8 * j];
            s.x += v.x; s.y += v.y; s.z += v.z; s.w += v.w;
        }
        *reinterpret_cast<float4*>(&g_partial[blockIdx.x][tid * 4]) = s;
    }
    __syncthreads();

    acc = make_float4(0.f, 0.f, 0.f, 0.f);
    for (int i = blockIdx.x * 256 + tid; i < n1_4; i += 64 * 256) {
        float4 v = U1[i];
        acc.x += v.x; acc.y += v.y; acc.z += v.z; acc.w += v.w;
    }
    red[tid] = acc;
    __syncthreads();
    if (tid < 8) {
        float4 s = make_float4(0.f, 0.f, 0.f, 0.f);
#pragma unroll
        for (int j = 0; j < 32; j++) {
            float4 v = red[tid + 8 * j];
            s.x += v.x; s.y += v.y; s.z += v.z; s.w += v.w;
        }
        *reinterpret_cast<float4*>(&g_partial[blockIdx.x][32 + tid * 4]) = s;
    }
}

__device__ __forceinline__ uint32_t f2tf32(float x) {
    uint32_t r;
    asm("cvt.rna.tf32.f32 %0, %1;" : "=r"(r) : "f"(x));
    return r;
}

// ---------------------------------------------------------------------------
// Prescale: reduce partials (fixed order) and write U0*s1 / U1*s0 as tf32
// bits into padded scratch. Pad rows (>=N) are zero-filled.
// 64 blocks x 256 threads; 2048*8 f4 slots for scr0, 1024*8 for scr1.
// ---------------------------------------------------------------------------
__global__ void prescale(const float4* __restrict__ U0, int n0,
                         const float4* __restrict__ U1, int n1) {
    __shared__ __align__(16) float sred[64];
    const int tid = threadIdx.x;
    if (tid < 64) {
        float s = 0.0f;
#pragma unroll
        for (int b = 0; b < 64; b++) s += g_partial[b][tid];
        sred[tid] = s;
    }
    __syncthreads();

    for (int i = blockIdx.x * 256 + tid; i < 2048 * 8; i += 64 * 256) {
        int row = i >> 3;
        int q = i & 7;
        float4 v = make_float4(0.f, 0.f, 0.f, 0.f);
        if (row < n0) v = U0[i];
        float4 s = *reinterpret_cast<const float4*>(&sred[32 + q * 4]);   // s1
        uint4 o = make_uint4(f2tf32(v.x * s.x), f2tf32(v.y * s.y),
                             f2tf32(v.z * s.z), f2tf32(v.w * s.w));
        *reinterpret_cast<uint4*>(&g_scr0[i * 4]) = o;
    }
    for (int i = blockIdx.x * 256 + tid; i < 1024 * 8; i += 64 * 256) {
        int row = i >> 3;
        int q = i & 7;
        float4 v = make_float4(0.f, 0.f, 0.f, 0.f);
        if (row < n1) v = U1[i];
        float4 s = *reinterpret_cast<const float4*>(&sred[q * 4]);        // s0
        uint4 o = make_uint4(f2tf32(v.x * s.x), f2tf32(v.y * s.y),
                             f2tf32(v.z * s.z), f2tf32(v.w * s.w));
        *reinterpret_cast<uint4*>(&g_scr1[i * 4]) = o;
    }
}

// ---------------------------------------------------------------------------
// helpers
// ---------------------------------------------------------------------------
__device__ __forceinline__ uint32_t smem_u32(const void* p) {
    uint32_t a;
    asm("{ .reg .u64 t; cvta.to.shared.u64 t, %1; cvt.u32.u64 %0, t; }"
        : "=r"(a) : "l"(p));
    return a;
}
__device__ __forceinline__ void mma_tf32(
    float& c0, float& c1, float& c2, float& c3,
    uint32_t a0, uint32_t a1, uint32_t a2, uint32_t a3,
    uint32_t b0, uint32_t b1) {
    asm volatile(
        "mma.sync.aligned.m16n8k8.row.col.f32.tf32.tf32.f32 "
        "{%0,%1,%2,%3}, {%4,%5,%6,%7}, {%8,%9}, {%0,%1,%2,%3};"
        : "+f"(c0), "+f"(c1), "+f"(c2), "+f"(c3)
        : "r"(a0), "r"(a1), "r"(a2), "r"(a3), "r"(b0), "r"(b1));
}

// ---------------------------------------------------------------------------
// Fused GEMM, BM=64, register-resident A, LDGSTS B (prescaled tf32 scratch),
// warp-autonomous TMA-store epilogue.
// SMEM from 1024B-aligned ABSOLUTE base:
//   boxes 8 x 4KB (Atmp overlays, prologue only) | Bs0 16KB | Bs1 16KB.
// ---------------------------------------------------------------------------
__global__ __launch_bounds__(256, 2) void gemm_fused(
    const float* __restrict__ A, int P,
    const __grid_constant__ CUtensorMap tm0,
    const __grid_constant__ CUtensorMap tm1) {
    extern __shared__ float smf[];
    const uint32_t dynbase = smem_u32(smf);
    const uint32_t abase = (dynbase + 1023u) & ~1023u;
    uint8_t* basep = reinterpret_cast<uint8_t*>(smf) + (abase - dynbase);
    float* Atmp = reinterpret_cast<float*>(basep);               // [64][33], one-time
    uint32_t* Bs0 = reinterpret_cast<uint32_t*>(basep + 32768);
    uint32_t* Bs1 = reinterpret_cast<uint32_t*>(basep + 49152);
    const uint32_t bs0_addr = abase + 32768;
    const uint32_t bs1_addr = abase + 49152;

    const int tid = threadIdx.x;
    const int x = blockIdx.x;
    const int p0 = blockIdx.y * 64;

    const uint32_t* scr = (x == 2) ? g_scr1 : g_scr0;
    const CUtensorMap* tmap = (x == 2) ? &tm1 : &tm0;
    const int tc0 = (x == 2) ? 0 : x * 8;

    const int kq = tid & 7;
    const int rbase = tid >> 3;
    // Per-thread LDGSTS smem offsets (quad-XOR swizzle), fixed across tiles.
    uint32_t bofs[4];
#pragma unroll
    for (int it = 0; it < 4; it++) {
        int row = it * 32 + rbase;
        bofs[it] = (uint32_t)((row * 32 + ((kq ^ (row & 7)) << 2)) * 4);
    }

    // ---- Load A stripe (64 x 32 raw) into Atmp [row][33] ----
#pragma unroll
    for (int it = 0; it < 2; it++) {
        int slot = it * 256 + tid;
        int row = slot >> 3;
        int q = slot & 7;
        float4 v = make_float4(0.f, 0.f, 0.f, 0.f);
        if (p0 + row < P)
            v = *reinterpret_cast<const float4*>(A + (size_t)(p0 + row) * 32 + q * 4);
        float* dst = Atmp + row * 33 + q * 4;
        dst[0] = v.x; dst[1] = v.y; dst[2] = v.z; dst[3] = v.w;
    }

    // ---- LDGSTS B tile 0 into Bs0 ----
#pragma unroll
    for (int it = 0; it < 4; it++) {
        int row = it * 32 + rbase;
        const uint32_t* src = scr + (size_t)(tc0 * 128 + row) * 32 + kq * 4;
        asm volatile("cp.async.cg.shared.global [%0], [%1], 16;"
                     :: "r"(bs0_addr + bofs[it]), "l"(src) : "memory");
    }
    asm volatile("cp.async.commit_group;" ::: "memory");
    __syncthreads();   // Atmp fully written

    const int wid = tid >> 5;
    const int lane = tid & 31;
    const int gid = lane >> 2;
    const int tig = lane & 3;
    const int mb = (wid & 1) * 32;
    const int nb = (wid >> 1) * 32;

    // ---- Distribute A fragments to registers (held for all 8 tiles) ----
    uint32_t a[2][4][4];
#pragma unroll
    for (int mt = 0; mt < 2; mt++) {
        int r0 = mb + mt * 16 + gid;
#pragma unroll
        for (int kk = 0; kk < 4; kk++) {
            int k = kk * 8 + tig;
            a[mt][kk][0] = f2tf32(Atmp[r0 * 33 + k]);
            a[mt][kk][1] = f2tf32(Atmp[(r0 + 8) * 33 + k]);
            a[mt][kk][2] = f2tf32(Atmp[r0 * 33 + k + 4]);
            a[mt][kk][3] = f2tf32(Atmp[(r0 + 8) * 33 + k + 4]);
        }
    }
    asm volatile("cp.async.wait_group 0;" ::: "memory");
    __syncthreads();   // Bs0 ready; Atmp reads done -> boxes free

    uint8_t* mybuf = basep + wid * 4096;
    const uint32_t mybuf_addr = abase + wid * 4096;

    for (int t = 0; t < 8; t++) {
        uint32_t* Bcur = (t & 1) ? Bs1 : Bs0;
        const uint32_t bnxt_addr = (t & 1) ? bs0_addr : bs1_addr;
        const int n0 = (tc0 + t) * 128;

        // LDGSTS next B tile into the other buffer (overlaps compute+epilogue)
        if (t < 7) {
#pragma unroll
            for (int it = 0; it < 4; it++) {
                int row = it * 32 + rbase;
                const uint32_t* src = scr + (size_t)(n0 + 128 + row) * 32 + kq * 4;
                asm volatile("cp.async.cg.shared.global [%0], [%1], 16;"
                             :: "r"(bnxt_addr + bofs[it]), "l"(src) : "memory");
            }
            asm volatile("cp.async.commit_group;" ::: "memory");
        }

        float c[2][4][4];
#pragma unroll
        for (int mt = 0; mt < 2; mt++)
#pragma unroll
            for (int nt = 0; nt < 4; nt++)
#pragma unroll
                for (int r = 0; r < 4; r++) c[mt][nt][r] = 0.0f;

#pragma unroll
        for (int kk = 0; kk < 4; kk++) {
            const int w0 = (((kk * 2) ^ gid) << 2) + tig;
            const int w1 = (((kk * 2 + 1) ^ gid) << 2) + tig;
            uint32_t b[4][2];
#pragma unroll
            for (int nt = 0; nt < 4; nt++) {
                int n = nb + nt * 8;
                b[nt][0] = Bcur[(n + gid) * 32 + w0];
                b[nt][1] = Bcur[(n + gid) * 32 + w1];
            }
#pragma unroll
            for (int mt = 0; mt < 2; mt++)
#pragma unroll
                for (int nt = 0; nt < 4; nt++)
                    mma_tf32(c[mt][nt][0], c[mt][nt][1], c[mt][nt][2], c[mt][nt][3],
                             a[mt][kk][0], a[mt][kk][1], a[mt][kk][2], a[mt][kk][3],
                             b[nt][0], b[nt][1]);
        }

        // ---- Warp-autonomous epilogue: stage 32x32 box + one TMA store ----
        if (lane == 0)
            asm volatile("cp.async.bulk.wait_group.read 0;" ::: "memory");
        __syncwarp();
#pragma unroll
        for (int mt = 0; mt < 2; mt++) {
#pragma unroll
            for (int nt = 0; nt < 4; nt++) {
                uint32_t off0 = (uint32_t)((mt * 16 + gid) * 128 + nt * 32 + tig * 8);
                uint32_t sw0 = off0 ^ ((off0 >> 3) & 0x70);
                *reinterpret_cast<float2*>(mybuf + sw0) =
                    make_float2(c[mt][nt][0], c[mt][nt][1]);
                uint32_t off1 = off0 + 8 * 128;
                uint32_t sw1 = off1 ^ ((off1 >> 3) & 0x70);
                *reinterpret_cast<float2*>(mybuf + sw1) =
                    make_float2(c[mt][nt][2], c[mt][nt][3]);
            }
        }
        __syncwarp();
        if (lane == 0) {
            asm volatile("fence.proxy.async.shared::cta;" ::: "memory");
            asm volatile(
                "cp.async.bulk.tensor.2d.global.shared::cta.tile.bulk_group "
                "[%0, {%1, %2}], [%3];"
                :: "l"(tmap), "r"(n0 + nb), "r"(p0 + mb), "r"(mybuf_addr)
                : "memory");
            asm volatile("cp.async.bulk.commit_group;" ::: "memory");
        }

        // ---- Flip to next B tile ----
        if (t < 7) {
            asm volatile("cp.async.wait_group 0;" ::: "memory");
            __syncthreads();   // Bnxt ready, all warps done with Bcur
        }
    }

    if (lane == 0)
        asm volatile("cp.async.bulk.wait_group 0;" ::: "memory");
}

// ---------------------------------------------------------------------------
typedef CUresult (*EncodeTiledFn)(
    CUtensorMap*, CUtensorMapDataType, cuuint32_t, void*,
    const cuuint64_t*, const cuuint64_t*, const cuuint32_t*, const cuuint32_t*,
    CUtensorMapInterleave, CUtensorMapSwizzle, CUtensorMapL2promotion,
    CUtensorMapFloatOOBfill);

extern "C" void kernel_launch(void* const* d_in, const int* in_sizes, int n_in,
                              void* d_out, int out_size) {
    const float* pt = (const float*)d_in[0];  // [P, 32]
    const float* U0 = (const float*)d_in[1];  // [N0, 32]
    const float* U1 = (const float*)d_in[2];  // [N1, 32]
    const int P  = in_sizes[0] / 32;
    const int N0 = in_sizes[1] / 32;
    const int N1 = in_sizes[2] / 32;

    float* V0 = (float*)d_out;
    float* V1 = V0 + (size_t)P * N0;

    void* sym = nullptr;
    cudaDriverEntryPointQueryResult qr;
    cudaGetDriverEntryPointByVersion("cuTensorMapEncodeTiled", &sym, 12000,
                                     cudaEnableDefault, &qr);
    EncodeTiledFn enc = (EncodeTiledFn)sym;

    CUtensorMap tm0, tm1;
    {
        cuuint64_t dims[2]  = {(cuuint64_t)N0, (cuuint64_t)P};
        cuuint64_t strides[1] = {(cuuint64_t)N0 * 4};
        cuuint32_t box[2]   = {32, 32};
        cuuint32_t es[2]    = {1, 1};
        enc(&tm0, CU_TENSOR_MAP_DATA_TYPE_FLOAT32, 2, (void*)V0, dims, strides,
            box, es, CU_TENSOR_MAP_INTERLEAVE_NONE, CU_TENSOR_MAP_SWIZZLE_128B,
            CU_TENSOR_MAP_L2_PROMOTION_L2_128B, CU_TENSOR_MAP_FLOAT_OOB_FILL_NONE);
    }
    {
        cuuint64_t dims[2]  = {(cuuint64_t)N1, (cuuint64_t)P};
        cuuint64_t strides[1] = {(cuuint64_t)N1 * 4};
        cuuint32_t box[2]   = {32, 32};
        cuuint32_t es[2]    = {1, 1};
        enc(&tm1, CU_TENSOR_MAP_DATA_TYPE_FLOAT32, 2, (void*)V1, dims, strides,
            box, es, CU_TENSOR_MAP_INTERLEAVE_NONE, CU_TENSOR_MAP_SWIZZLE_128B,
            CU_TENSOR_MAP_L2_PROMOTION_L2_128B, CU_TENSOR_MAP_FLOAT_OOB_FILL_NONE);
    }

    // 1KB slack + 8 x 4KB boxes + Bs0 16KB + Bs1 16KB
    const int smem_bytes = 1024 + 32768 + 16384 + 16384;   // 66560
    cudaFuncSetAttribute(gemm_fused, cudaFuncAttributeMaxDynamicSharedMemorySize,
                         smem_bytes);

    colsum_stage1<<<64, 256>>>((const float4*)U0, in_sizes[1] / 4,
                               (const float4*)U1, in_sizes[2] / 4);
    prescale<<<64, 256>>>((const float4*)U0, N0, (const float4*)U1, N1);

    dim3 grid(3, (P + 63) / 64);
    gemm_fused<<<grid, 256, smem_bytes>>>(pt, P, tm0, tm1);
}